// round 2
// baseline (speedup 1.0000x reference)
#include <cuda_runtime.h>
#include <cstdint>

typedef unsigned long long u64;

#define BATCH 16
#define CHAN  256
#define H     64
#define W     64
#define MAXD  4
#define PATCH 9
#define ITILE 2   // output rows per block

__device__ __forceinline__ u64 pack2(float lo, float hi) {
    u64 d;
    asm("mov.b64 %0, {%1,%2};" : "=l"(d) : "f"(lo), "f"(hi));
    return d;
}
__device__ __forceinline__ void unpack2(u64 v, float &lo, float &hi) {
    asm("mov.b64 {%0,%1}, %2;" : "=f"(lo), "=f"(hi) : "l"(v));
}
__device__ __forceinline__ void ffma2(u64 &d, u64 a, u64 b) {
    // packed fp32x2 FMA: d.lo += a.lo*b.lo ; d.hi += a.hi*b.hi
    asm("fma.rn.f32x2 %0, %1, %2, %0;" : "+l"(d) : "l"(a), "l"(b));
}

// Block: (b, i0) tile of ITILE=2 output rows. 9 warps, warp = di.
// lane: il = lane>>4 (row within tile), jseg = lane&15, thread owns 4 px
// j0..j0+3 and all 9 dj for them. All LDG.128 are lane-contiguous.
__global__ __launch_bounds__(288, 3)
void corr_kernel(const float* __restrict__ x,
                 const float* __restrict__ y,
                 float* __restrict__ out)
{
    const int b    = blockIdx.x >> 5;            // 32 i-tiles per batch
    const int i0   = (blockIdx.x & 31) * ITILE;
    const int di   = threadIdx.x >> 5;           // warp id: 0..8
    const int lane = threadIdx.x & 31;
    const int il   = lane >> 4;
    const int jseg = lane & 15;
    const int j0   = jseg * 4;
    const int i    = i0 + il;
    const int yi   = i + di - MAXD;
    const bool rowv = (yi >= 0) && (yi < H);

    const float* xp = x + (((size_t)b * CHAN) * H + i) * W + j0;
    const float* yp = y + (((size_t)b * CHAN) * H + (rowv ? yi : 0)) * W + (j0 - MAXD);

    // y window q[0..11] = y[yi, j0-4 .. j0+7]; three 16B-aligned 4-float chunks,
    // each all-or-nothing valid:
    const bool cv0 = rowv && (jseg > 0);    // q[0..3]  = y[j0-4..j0-1]
    const bool cv1 = rowv;                  // q[4..7]  = y[j0..j0+3]
    const bool cv2 = rowv && (jseg < 15);   // q[8..11] = y[j0+4..j0+7]

    u64 acc[2][PATCH];
    #pragma unroll
    for (int t = 0; t < 2; t++)
        #pragma unroll
        for (int dj = 0; dj < PATCH; dj++) acc[t][dj] = 0ull;

    const float4 Z = make_float4(0.f, 0.f, 0.f, 0.f);

    #pragma unroll 2
    for (int c = 0; c < CHAN; c++) {
        // ---- loads first: 4 independent LDG.128, all lane-contiguous ----
        float4 xv = *reinterpret_cast<const float4*>(xp);
        float4 y0 = cv0 ? *reinterpret_cast<const float4*>(yp)     : Z;
        float4 y1 = cv1 ? *reinterpret_cast<const float4*>(yp + 4) : Z;
        float4 y2 = cv2 ? *reinterpret_cast<const float4*>(yp + 8) : Z;

        u64 xq0 = pack2(xv.x, xv.y);
        u64 xq1 = pack2(xv.z, xv.w);

        // pair P[k] = (q[k], q[k+1]), k = 0..10
        u64 P[11];
        P[0]  = pack2(y0.x, y0.y);
        P[1]  = pack2(y0.y, y0.z);
        P[2]  = pack2(y0.z, y0.w);
        P[3]  = pack2(y0.w, y1.x);
        P[4]  = pack2(y1.x, y1.y);
        P[5]  = pack2(y1.y, y1.z);
        P[6]  = pack2(y1.z, y1.w);
        P[7]  = pack2(y1.w, y2.x);
        P[8]  = pack2(y2.x, y2.y);
        P[9]  = pack2(y2.y, y2.z);
        P[10] = pack2(y2.z, y2.w);

        // acc[t][dj] += (x[j0+2t], x[j0+2t+1]) * P[2t+dj]   (18 FFMA2)
        #pragma unroll
        for (int k = 0; k < 11; k++) {
            if (k <= 8) ffma2(acc[0][k],     xq0, P[k]);
            if (k >= 2) ffma2(acc[1][k - 2], xq1, P[k]);
        }

        xp += H * W;
        yp += H * W;
    }

    // ---- epilogue: scale by 1/C, one float4 store per dj ----
    const float inv = 1.0f / (float)CHAN;
    float* op = out + ((((size_t)b * (PATCH * PATCH)) + (size_t)di * PATCH) * H + i) * W + j0;
    #pragma unroll
    for (int dj = 0; dj < PATCH; dj++) {
        float4 v;
        unpack2(acc[0][dj], v.x, v.y);
        unpack2(acc[1][dj], v.z, v.w);
        v.x *= inv; v.y *= inv; v.z *= inv; v.w *= inv;
        *reinterpret_cast<float4*>(op) = v;
        op += H * W;
    }
}

extern "C" void kernel_launch(void* const* d_in, const int* in_sizes, int n_in,
                              void* d_out, int out_size)
{
    const float* x = (const float*)d_in[0];
    const float* y = (const float*)d_in[1];
    float* out = (float*)d_out;
    dim3 grid(BATCH * (H / ITILE));   // 512 blocks
    dim3 block(32 * PATCH);           // 288 threads = 9 warps
    corr_kernel<<<grid, block>>>(x, y, out);
}

// round 3
// speedup vs baseline: 1.3036x; 1.3036x over previous
#include <cuda_runtime.h>
#include <cstdint>

typedef unsigned long long u64;

#define BATCH 16
#define CHAN  256
#define H     64
#define W     64
#define HW    (H * W)
#define MAXD  4
#define PATCH 9
#define ITILE 2   // output rows per block

__device__ __forceinline__ u64 pack2(float lo, float hi) {
    u64 d;
    asm("mov.b64 %0, {%1,%2};" : "=l"(d) : "f"(lo), "f"(hi));
    return d;
}
__device__ __forceinline__ void unpack2(u64 v, float &lo, float &hi) {
    asm("mov.b64 {%0,%1}, %2;" : "=f"(lo), "=f"(hi) : "l"(v));
}
__device__ __forceinline__ void ffma2(u64 &d, u64 a, u64 b) {
    asm("fma.rn.f32x2 %0, %1, %2, %0;" : "+l"(d) : "l"(a), "l"(b));
}

// Block: (b, i0) tile of ITILE=2 rows. 9 warps, warp = di.
// lane: il = lane>>4, jseg = lane&15, thread owns 4 px (j0..j0+3), all 9 dj.
// Parity-paired accumulators:
//   even dj (e=dj/2):  accE0[e]=(o0,o1), accE1[e]=(o2,o3)
//   odd  dj (o):       accO[o]=(o1,o2),  accS0[o]=o0, accS3[o]=o3
// y pairs are ALWAYS even-aligned -> zero pack MOVs for y.
__global__ __launch_bounds__(288, 3)
void corr_kernel(const float* __restrict__ x,
                 const float* __restrict__ y,
                 float* __restrict__ out)
{
    const int b    = blockIdx.x >> 5;
    const int i0   = (blockIdx.x & 31) * ITILE;
    const int di   = threadIdx.x >> 5;
    const int lane = threadIdx.x & 31;
    const int il   = lane >> 4;
    const int jseg = lane & 15;
    const int j0   = jseg * 4;
    const int i    = i0 + il;
    const int yi   = i + di - MAXD;
    const bool rowv = (yi >= 0) && (yi < H);

    const float* xp = x + (((size_t)b * CHAN) * H + i) * W + j0;
    const float* yp = y + (((size_t)b * CHAN) * H + (rowv ? yi : 0)) * W + (j0 - MAXD);

    const bool cv0 = rowv && (jseg > 0);    // yq[0..3]  = y[j0-4..j0-1]
    const bool cv1 = rowv;                  // yq[4..7]  = y[j0..j0+3]
    const bool cv2 = rowv && (jseg < 15);   // yq[8..11] = y[j0+4..j0+7]

    u64 accE0[5], accE1[5], accO[4];
    float accS0[4], accS3[4];
    #pragma unroll
    for (int e = 0; e < 5; e++) { accE0[e] = 0ull; accE1[e] = 0ull; }
    #pragma unroll
    for (int o = 0; o < 4; o++) { accO[o] = 0ull; accS0[o] = 0.f; accS3[o] = 0.f; }

    const float4 Z = make_float4(0.f, 0.f, 0.f, 0.f);

    #pragma unroll 4
    for (int c = 0; c < CHAN; c++) {
        // 4 coalesced LDG.128 (lane-contiguous within each row half)
        float4 xv = *reinterpret_cast<const float4*>(xp);
        float4 ya = cv0 ? *reinterpret_cast<const float4*>(yp)     : Z;
        float4 yb = cv1 ? *reinterpret_cast<const float4*>(yp + 4) : Z;
        float4 yc = cv2 ? *reinterpret_cast<const float4*>(yp + 8) : Z;

        // even-aligned pairs (register-pair views, no data movement needed)
        u64 P0 = pack2(ya.x, ya.y);
        u64 P1 = pack2(ya.z, ya.w);
        u64 P2 = pack2(yb.x, yb.y);
        u64 P3 = pack2(yb.z, yb.w);
        u64 P4 = pack2(yc.x, yc.y);
        u64 P5 = pack2(yc.z, yc.w);
        u64 Pm[6] = { P0, P1, P2, P3, P4, P5 };

        u64 XE0 = pack2(xv.x, xv.y);   // aligned: free
        u64 XE1 = pack2(xv.z, xv.w);   // aligned: free
        u64 XO  = pack2(xv.y, xv.z);   // the only real pack (2 MOV)

        // even dj: s = 2e-4
        #pragma unroll
        for (int e = 0; e < 5; e++) {
            ffma2(accE0[e], XE0, Pm[e]);
            ffma2(accE1[e], XE1, Pm[e + 1]);
        }
        // odd dj: s = 2o-3
        #pragma unroll
        for (int o = 0; o < 4; o++) {
            ffma2(accO[o], XO, Pm[o + 1]);
        }
        // scalar edges for odd dj: o0 += x0*yq[2o+1], o3 += x3*yq[2o+4]
        accS0[0] = fmaf(xv.x, ya.y, accS0[0]);
        accS0[1] = fmaf(xv.x, ya.w, accS0[1]);
        accS0[2] = fmaf(xv.x, yb.y, accS0[2]);
        accS0[3] = fmaf(xv.x, yb.w, accS0[3]);
        accS3[0] = fmaf(xv.w, yb.x, accS3[0]);
        accS3[1] = fmaf(xv.w, yb.z, accS3[1]);
        accS3[2] = fmaf(xv.w, yc.x, accS3[2]);
        accS3[3] = fmaf(xv.w, yc.z, accS3[3]);

        xp += HW;
        yp += HW;
    }

    // ---- epilogue ----
    const float inv = 1.0f / (float)CHAN;
    float* op = out + ((((size_t)b * (PATCH * PATCH)) + (size_t)di * PATCH) * H + i) * W + j0;
    #pragma unroll
    for (int dj = 0; dj < PATCH; dj++) {
        float4 v;
        if ((dj & 1) == 0) {
            const int e = dj >> 1;
            unpack2(accE0[e], v.x, v.y);
            unpack2(accE1[e], v.z, v.w);
        } else {
            const int o = dj >> 1;
            v.x = accS0[o];
            unpack2(accO[o], v.y, v.z);
            v.w = accS3[o];
        }
        v.x *= inv; v.y *= inv; v.z *= inv; v.w *= inv;
        *reinterpret_cast<float4*>(op) = v;
        op += HW;
    }
}

extern "C" void kernel_launch(void* const* d_in, const int* in_sizes, int n_in,
                              void* d_out, int out_size)
{
    const float* x = (const float*)d_in[0];
    const float* y = (const float*)d_in[1];
    float* out = (float*)d_out;
    dim3 grid(BATCH * (H / ITILE));   // 512 blocks
    dim3 block(32 * PATCH);           // 288 threads = 9 warps
    corr_kernel<<<grid, block>>>(x, y, out);
}

// round 5
// speedup vs baseline: 3.3030x; 2.5337x over previous
#include <cuda_runtime.h>
#include <cstdint>

typedef unsigned long long u64;

#define BATCH 16
#define CHAN  256
#define H     64
#define W     64
#define HW    (H * W)
#define MAXD  4
#define PATCH 9
#define ITILE 2

#define CC      4                 // channels per pipeline stage
#define NCHUNK  (CHAN / CC)       // 64
#define YROWS   (ITILE + 2*MAXD)  // 10
#define YPITCH  72                // 4 zero-pad + 64 + 4 zero-pad
#define XS      (CC * ITILE * W)          // 512 floats
#define YSLAB   (CC * YROWS * YPITCH)     // 2880 floats
#define BUFF    (XS + YSLAB)              // 3392 floats per buffer
#define NELEM   (CC*ITILE*(W/4) + CC*YROWS*(W/4))  // 128 + 640 = 768 cp.async/chunk

__device__ __forceinline__ u64 pack2(float lo, float hi) {
    u64 d; asm("mov.b64 %0, {%1,%2};" : "=l"(d) : "f"(lo), "f"(hi)); return d;
}
__device__ __forceinline__ void unpack2(u64 v, float &lo, float &hi) {
    asm("mov.b64 {%0,%1}, %2;" : "=f"(lo), "=f"(hi) : "l"(v));
}
__device__ __forceinline__ void ffma2(u64 &d, u64 a, u64 b) {
    asm("fma.rn.f32x2 %0, %1, %2, %0;" : "+l"(d) : "l"(a), "l"(b));
}

// Block: (b, i0) tile of 2 rows. 9 warps, warp = di.
// lane: il = lane>>4 (row), jseg = lane&15, thread owns 4 px, all 9 dj.
__global__ __launch_bounds__(288, 3)
void corr_kernel(const float* __restrict__ x,
                 const float* __restrict__ y,
                 float* __restrict__ out)
{
    __shared__ float smem[2][BUFF];

    const int tid  = threadIdx.x;
    const int b    = blockIdx.x >> 5;
    const int i0   = (blockIdx.x & 31) * ITILE;
    const int di   = tid >> 5;
    const int lane = tid & 31;
    const int il   = lane >> 4;
    const int jseg = lane & 15;
    const int j0   = jseg * 4;
    const int i    = i0 + il;

    // ---- zero the static y pads (cols 0..3 and 68..71), both buffers ----
    for (int z = tid; z < 2 * CC * YROWS * 8; z += 288) {
        int buf  = z / (CC * YROWS * 8);
        int rem  = z - buf * (CC * YROWS * 8);
        int ch   = rem / (YROWS * 8);
        int rem2 = rem - ch * (YROWS * 8);
        int r    = rem2 >> 3;
        int p    = rem2 & 7;
        int col  = (p < 4) ? p : (64 + p);
        smem[buf][XS + ch * (YROWS * YPITCH) + r * YPITCH + col] = 0.f;
    }

    // ---- precompute cp.async fill slots (warp-uniform count: 3 or 2) ----
    const int nslot = (tid < 192) ? 3 : 2;   // 768 = 192*3 + 96*2
    uint32_t     s_off[3];
    const float* g_ptr[3];
    uint32_t     s_sz[3];
    {
        const float* xbase = x + ((size_t)b * CHAN) * HW + (size_t)i0 * W;
        const float* ybase = y + ((size_t)b * CHAN) * HW;
        #pragma unroll
        for (int s = 0; s < 3; s++) {
            int e = tid + s * 288;
            if (e >= NELEM) e = 0;           // dead slot (never issued)
            if (e < 128) {                   // x element
                int ch = e >> 5, r = (e >> 4) & 1, seg = e & 15;
                s_off[s] = (uint32_t)(ch * (ITILE * W) + r * W + seg * 4) * 4u;
                g_ptr[s] = xbase + ch * HW + r * W + seg * 4;
                s_sz[s]  = 16;
            } else {                         // y element
                int e2 = e - 128;
                int ch = e2 / 160, rem = e2 - ch * 160;
                int r = rem >> 4, seg = rem & 15;
                int yr = i0 - MAXD + r;
                bool v = (yr >= 0) && (yr < H);
                s_off[s] = (uint32_t)(XS + ch * (YROWS * YPITCH) + r * YPITCH + 4 + seg * 4) * 4u;
                g_ptr[s] = ybase + ch * HW + (v ? yr : 0) * W + seg * 4;
                s_sz[s]  = v ? 16u : 0u;     // 0 -> zero-fill 16B
            }
        }
    }

    const uint32_t sm0 = (uint32_t)__cvta_generic_to_shared(&smem[0][0]);

    auto do_fill = [&](int buf) {
        uint32_t base = sm0 + (uint32_t)buf * (BUFF * 4);
        #pragma unroll
        for (int s = 0; s < 3; s++) {
            if (s < nslot) {
                asm volatile("cp.async.cg.shared.global [%0], [%1], 16, %2;"
                             :: "r"(base + s_off[s]), "l"(g_ptr[s]), "r"(s_sz[s]));
                g_ptr[s] += CC * HW;
            }
        }
    };

    // ---- accumulators (parity-paired) ----
    u64 accE0[5], accE1[5], accO[4];
    float accS0[4], accS3[4];
    #pragma unroll
    for (int e = 0; e < 5; e++) { accE0[e] = 0ull; accE1[e] = 0ull; }
    #pragma unroll
    for (int o = 0; o < 4; o++) { accO[o] = 0ull; accS0[o] = 0.f; accS3[o] = 0.f; }

    __syncthreads();               // pads visible before first compute

    do_fill(0);
    asm volatile("cp.async.commit_group;" ::: "memory");
    do_fill(1);
    asm volatile("cp.async.commit_group;" ::: "memory");

    const float* xs0 = &smem[0][il * W + j0];
    const float* ys0 = &smem[0][XS + (il + di) * YPITCH + jseg * 4];

    for (int k = 0; k < NCHUNK; k++) {
        asm volatile("cp.async.wait_group 1;" ::: "memory");
        __syncthreads();

        const int buf = k & 1;
        const float* xs = xs0 + buf * BUFF;
        const float* ys = ys0 + buf * BUFF;

        #pragma unroll
        for (int ch = 0; ch < CC; ch++) {
            float4 xv = *reinterpret_cast<const float4*>(xs + ch * (ITILE * W));
            float4 ya = *reinterpret_cast<const float4*>(ys + ch * (YROWS * YPITCH));
            float4 yb = *reinterpret_cast<const float4*>(ys + ch * (YROWS * YPITCH) + 4);
            float4 yc = *reinterpret_cast<const float4*>(ys + ch * (YROWS * YPITCH) + 8);

            u64 Pm[6];
            Pm[0] = pack2(ya.x, ya.y);
            Pm[1] = pack2(ya.z, ya.w);
            Pm[2] = pack2(yb.x, yb.y);
            Pm[3] = pack2(yb.z, yb.w);
            Pm[4] = pack2(yc.x, yc.y);
            Pm[5] = pack2(yc.z, yc.w);

            u64 XE0 = pack2(xv.x, xv.y);
            u64 XE1 = pack2(xv.z, xv.w);
            u64 XO  = pack2(xv.y, xv.z);

            #pragma unroll
            for (int e = 0; e < 5; e++) {
                ffma2(accE0[e], XE0, Pm[e]);
                ffma2(accE1[e], XE1, Pm[e + 1]);
            }
            #pragma unroll
            for (int o = 0; o < 4; o++) ffma2(accO[o], XO, Pm[o + 1]);

            accS0[0] = fmaf(xv.x, ya.y, accS0[0]);
            accS0[1] = fmaf(xv.x, ya.w, accS0[1]);
            accS0[2] = fmaf(xv.x, yb.y, accS0[2]);
            accS0[3] = fmaf(xv.x, yb.w, accS0[3]);
            accS3[0] = fmaf(xv.w, yb.x, accS3[0]);
            accS3[1] = fmaf(xv.w, yb.z, accS3[1]);
            accS3[2] = fmaf(xv.w, yc.x, accS3[2]);
            accS3[3] = fmaf(xv.w, yc.z, accS3[3]);
        }

        __syncthreads();
        if (k + 2 < NCHUNK) do_fill(buf);
        asm volatile("cp.async.commit_group;" ::: "memory");
    }

    // ---- epilogue: scale by 1/C, one float4 store per dj ----
    const float inv = 1.0f / (float)CHAN;
    float* op = out + ((((size_t)b * (PATCH * PATCH)) + (size_t)di * PATCH) * H + i) * W + j0;
    #pragma unroll
    for (int dj = 0; dj < PATCH; dj++) {
        float4 v;
        if ((dj & 1) == 0) {
            const int e = dj >> 1;
            unpack2(accE0[e], v.x, v.y);
            unpack2(accE1[e], v.z, v.w);
        } else {
            const int o = dj >> 1;
            v.x = accS0[o];
            unpack2(accO[o], v.y, v.z);
            v.w = accS3[o];
        }
        v.x *= inv; v.y *= inv; v.z *= inv; v.w *= inv;
        *reinterpret_cast<float4*>(op) = v;
        op += HW;
    }
}

extern "C" void kernel_launch(void* const* d_in, const int* in_sizes, int n_in,
                              void* d_out, int out_size)
{
    const float* x = (const float*)d_in[0];
    const float* y = (const float*)d_in[1];
    float* out = (float*)d_out;
    dim3 grid(BATCH * (H / ITILE));   // 512 blocks
    dim3 block(32 * PATCH);           // 288 threads = 9 warps
    corr_kernel<<<grid, block>>>(x, y, out);
}